// round 6
// baseline (speedup 1.0000x reference)
#include <cuda_runtime.h>
#include <math.h>

// ---------------- problem constants ----------------
#define BB   128
#define DD   512
#define SS   30
#define HW   196
#define TT   12
#define NH   13
#define BDSZ (BB*DD)
#define NBLK 128
#define NTHR 256

// ---------------- device state ----------------
__device__ unsigned g_bar;

__device__ float g_KBp[(size_t)BB*HW*DD];
__device__ float g_chist[(size_t)NH*BDSZ];
__device__ float g_mhist[(size_t)NH*BDSZ];
__device__ float g_qi[BDSZ];
__device__ float g_cq0[BDSZ];
__device__ float g_v[BDSZ];
__device__ float g_U[(size_t)BB*2*DD];
__device__ float g_mnew[BDSZ];
__device__ float g_msa[BDSZ];
__device__ float g_Wcomb[(size_t)3*DD*DD];
__device__ float g_bcomb[DD];
__device__ float g_p_cq[(size_t)4*BDSZ];
__device__ float g_p_mp[(size_t)4*BDSZ];
__device__ float g_p_U [(size_t)4*BB*2*DD];
__device__ float g_p_g [(size_t)4*BDSZ];
__device__ float g_p_z [(size_t)4*BDSZ];
__device__ float g_p_f [(size_t)12*BDSZ];

__global__ void reset_k() { g_bar = 0u; }

// ---------------- grid barrier (all 128 blocks resident by construction) ----------------
// Bounded spin: in a correct run the bound (~2e8 polls) is never approached;
// if co-residency were ever violated this fails fast instead of hanging the
// container at the 600s timeout.
__device__ __forceinline__ void gbar(unsigned &tgt)
{
    __syncthreads();
    tgt += NBLK;
    if (threadIdx.x == 0) {
        __threadfence();
        atomicAdd(&g_bar, 1u);
        long long spins = 0;
        while (*(volatile unsigned*)&g_bar < tgt) {
            __nanosleep(64);
            if (++spins > 200000000LL) break;
        }
        __threadfence();
    }
    __syncthreads();
}

// ---------------- 128x32 GEMM tile (partial or direct), KC k-range ----------------
// A pre-offset to k-base (k is the column dim, lda given). W pre-offset:
//   wtrans=0: W row-major (K,N), pre-offset by kbase*ldw
//   wtrans=1: W row-major (N,K), pre-offset by kbase
__device__ __noinline__ void gtile(
    const float* __restrict__ A, int lda, int m0,
    const float* __restrict__ W, int ldw, int wtrans,
    int n0, int KC,
    float* __restrict__ out, int ldo, const float* __restrict__ bias,
    float* sm)
{
    float (*As)[132] = (float(*)[132])sm;
    float (*Ws)[36]  = (float(*)[36])(sm + 16*132);
    int tid = threadIdx.x;
    int tx = tid & 7, tg = tid >> 3;
    int lm = tid >> 1, lk = (tid & 1) * 8;
    float acc[4][4];
#pragma unroll
    for (int i = 0; i < 4; i++)
#pragma unroll
        for (int j = 0; j < 4; j++) acc[i][j] = 0.f;

    for (int kt = 0; kt < KC; kt += 16) {
        const float* ap = A + (size_t)(m0 + lm) * lda + kt + lk;
        float4 a0 = *(const float4*)ap;
        float4 a1 = *(const float4*)(ap + 4);
        float w0, w1;
        if (wtrans) {
            int wn = tid >> 3, wk = (tid & 7) * 2;
            const float* wp = W + (size_t)(n0 + wn) * ldw + kt + wk;
            w0 = wp[0]; w1 = wp[1];
        } else {
            int wk = tid >> 4, wn = tid & 15;
            const float* wp = W + (size_t)(kt + wk) * ldw + n0 + wn;
            w0 = wp[0]; w1 = wp[16];
        }
        __syncthreads();
        As[lk+0][lm]=a0.x; As[lk+1][lm]=a0.y; As[lk+2][lm]=a0.z; As[lk+3][lm]=a0.w;
        As[lk+4][lm]=a1.x; As[lk+5][lm]=a1.y; As[lk+6][lm]=a1.z; As[lk+7][lm]=a1.w;
        if (wtrans) {
            int wn = tid >> 3, wk = (tid & 7) * 2;
            Ws[wk][wn] = w0; Ws[wk+1][wn] = w1;
        } else {
            int wk = tid >> 4, wn = tid & 15;
            Ws[wk][wn] = w0; Ws[wk][wn+16] = w1;
        }
        __syncthreads();
#pragma unroll
        for (int kk = 0; kk < 16; kk++) {
            float4 a = *(const float4*)&As[kk][tg*4];
            float4 w = *(const float4*)&Ws[kk][tx*4];
            acc[0][0]+=a.x*w.x; acc[0][1]+=a.x*w.y; acc[0][2]+=a.x*w.z; acc[0][3]+=a.x*w.w;
            acc[1][0]+=a.y*w.x; acc[1][1]+=a.y*w.y; acc[1][2]+=a.y*w.z; acc[1][3]+=a.y*w.w;
            acc[2][0]+=a.z*w.x; acc[2][1]+=a.z*w.y; acc[2][2]+=a.z*w.z; acc[2][3]+=a.z*w.w;
            acc[3][0]+=a.w*w.x; acc[3][1]+=a.w*w.y; acc[3][2]+=a.w*w.z; acc[3][3]+=a.w*w.w;
        }
    }
    float* po = out + (size_t)(m0 + tg*4) * ldo + n0 + tx*4;
#pragma unroll
    for (int i = 0; i < 4; i++) {
        float4 r = make_float4(acc[i][0], acc[i][1], acc[i][2], acc[i][3]);
        if (bias) {
            int c = n0 + tx*4;
            r.x += bias[c]; r.y += bias[c+1]; r.z += bias[c+2]; r.w += bias[c+3];
        }
        *(float4*)(po + (size_t)i * ldo) = r;
    }
}

// ---------------- transpose KB (B,D,HW) -> KBp (B,HW,D) ----------------
__global__ void transpose_kb_k(const float* __restrict__ KB, float* __restrict__ KBp)
{
    __shared__ float tile[32][33];
    int b = blockIdx.z;
    int hw0 = blockIdx.x * 32, d0 = blockIdx.y * 32;
    int tx = threadIdx.x, ty = threadIdx.y;
    const float* src = KB + (size_t)b * DD * HW;
#pragma unroll
    for (int j = 0; j < 4; j++) {
        int d = d0 + ty + j * 8;
        int hw = hw0 + tx;
        if (hw < HW) tile[ty + j * 8][tx] = src[(size_t)d * HW + hw];
    }
    __syncthreads();
    float* dst = KBp + (size_t)b * HW * DD;
#pragma unroll
    for (int j = 0; j < 4; j++) {
        int hw = hw0 + ty + j * 8;
        if (hw < HW) dst[(size_t)hw * DD + d0 + tx] = tile[tx][ty + j * 8];
    }
}

// ---------------- megakernel params ----------------
struct MP {
    const float *q, *cws, *Wq, *bq, *Wct, *bct, *wca, *Wm, *bm, *Wkb, *Wrm, *wra,
                *Wwm, *bwm, *wwa, *Wam, *bam, *Wg, *bg;
    float* out;
};

__global__ void __launch_bounds__(NTHR) mega_k(const MP P)
{
    __shared__ float sm[16*132 + 16*36];
    const int blk = blockIdx.x, tid = threadIdx.x;
    const int lane = tid & 31, warp = tid >> 5;
    unsigned tgt = 0;

    // ---- PreA: Wcomb rows 512..1535 = Wwm @ Wam_bot (M=1024, direct, KC=512) ----
    {
        int mt = blk >> 4, nt = blk & 15;
        gtile(P.Wwm, DD, mt * 128, P.Wam + (size_t)DD * DD, DD, 0, nt * 32, DD,
              g_Wcomb + (size_t)DD * DD, DD, nullptr, sm);
    }
    gbar(tgt);

    // ---- PreB: qi = q@Wq + bq (16 blocks) ; bcomb (16 blocks) ----
    if (blk < 16) {
        gtile(P.q, DD, 0, P.Wq, DD, 0, blk * 32, DD, g_qi, DD, P.bq, sm);
    } else if (blk < 32) {
        int n = (blk - 16) * 32 + (tid >> 3);
        int j0 = tid & 7;
        float s = 0.f;
        for (int j = j0; j < DD; j += 8)
            s += P.bwm[j] * P.Wam[(size_t)(DD + j) * DD + n];
        s += __shfl_down_sync(0xffffffffu, s, 4, 8);
        s += __shfl_down_sync(0xffffffffu, s, 2, 8);
        s += __shfl_down_sync(0xffffffffu, s, 1, 8);
        if (j0 == 0) g_bcomb[n] = s + P.bam[n];
    }
    gbar(tgt);

    // ---- PreC: cq0 = qi@Wct_top + bct ----
    if (blk < 16)
        gtile(g_qi, DD, 0, P.Wct, DD, 0, blk * 32, DD, g_cq0, DD, P.bct, sm);
    gbar(tgt);

    // ================= main recurrence =================
    for (int t = 0; t < TT; t++) {
        const float* chist_t  = g_chist + (size_t)t * BDSZ;
        const float* mhist_t  = g_mhist + (size_t)t * BDSZ;
        float*       chist_t1 = g_chist + (size_t)(t + 1) * BDSZ;
        float*       mhist_t1 = g_mhist + (size_t)(t + 1) * BDSZ;

        // ---- P1: cq partials (64 blocks) || mp partials (64 blocks), KC=128 ----
        {
            int b2 = blk & 63;
            int nt = b2 & 15, ch = b2 >> 4, kb = ch * 128;
            if (blk < 64)
                gtile(chist_t + kb, DD, 0, P.Wct + (size_t)(DD + kb) * DD, DD, 0,
                      nt * 32, 128, g_p_cq + (size_t)ch * BDSZ, DD, nullptr, sm);
            else
                gtile(mhist_t + kb, DD, 0, P.Wm + (size_t)kb * DD, DD, 0,
                      nt * 32, 128, g_p_mp + (size_t)ch * BDSZ, DD, nullptr, sm);
        }
        gbar(tgt);

        // ---- P2: control attention + write-unit self-attention (block = batch) ----
        {
            int b = blk;
            float* wred  = sm;         // 8*30
            float* cattn = sm + 240;   // 30
            float* wred2 = sm + 272;   // 8*12
            float* sattn = sm + 368;   // 12
            float accs[SS];
#pragma unroll
            for (int s = 0; s < SS; s++) accs[s] = 0.f;
#pragma unroll
            for (int i = 0; i < 2; i++) {
                int d = tid + i * 256;
                size_t j = (size_t)b * DD + d;
                float cqv = g_p_cq[j] + g_p_cq[BDSZ + j] + g_p_cq[2*BDSZ + j]
                          + g_p_cq[3*BDSZ + j] + g_cq0[j];
                float a = cqv * P.wca[d];
                const float* row = P.cws + j * SS;
#pragma unroll
                for (int s = 0; s < SS; s++) accs[s] += a * row[s];
            }
#pragma unroll
            for (int s = 0; s < SS; s++) {
                float x = accs[s];
                for (int off = 16; off; off >>= 1) x += __shfl_down_sync(~0u, x, off);
                if (lane == 0) wred[warp * SS + s] = x;
            }
            __syncthreads();
            if (warp == 0) {
                float val = -1e30f;
                if (lane < SS) {
                    val = 0.f;
#pragma unroll
                    for (int w = 0; w < 8; w++) val += wred[w * SS + lane];
                }
                float mx = val;
                for (int off = 16; off; off >>= 1) mx = fmaxf(mx, __shfl_xor_sync(~0u, mx, off));
                float e = (lane < SS) ? expf(val - mx) : 0.f;
                float tot = e;
                for (int off = 16; off; off >>= 1) tot += __shfl_xor_sync(~0u, tot, off);
                if (lane < SS) cattn[lane] = e / tot;
            }
            __syncthreads();
            float ci[2];
#pragma unroll
            for (int i = 0; i < 2; i++) {
                int d = tid + i * 256;
                const float* row = P.cws + ((size_t)b * DD + d) * SS;
                float c = 0.f;
#pragma unroll
                for (int s = 0; s < SS; s++) c += cattn[s] * row[s];
                ci[i] = c;
                chist_t1[(size_t)b * DD + d] = c;
                g_v[(size_t)b * DD + d] = c * P.wra[d];
            }
            float aw0 = ci[0] * P.wwa[tid];
            float aw1 = ci[1] * P.wwa[tid + 256];
            float acct[TT];
#pragma unroll
            for (int tp = 0; tp < TT; tp++) acct[tp] = 0.f;
            for (int tp = 0; tp <= t; tp++) {
                const float* ch = g_chist + (size_t)tp * BDSZ + (size_t)b * DD;
                acct[tp] = aw0 * ch[tid] + aw1 * ch[tid + 256];
            }
#pragma unroll
            for (int tp = 0; tp < TT; tp++) {
                float x = acct[tp];
                for (int off = 16; off; off >>= 1) x += __shfl_down_sync(~0u, x, off);
                if (lane == 0) wred2[warp * TT + tp] = x;
            }
            __syncthreads();
            if (tid == 0) {
                int ntv = t + 1;
                float sl[TT];
                float mx = -1e30f;
                for (int tp = 0; tp < ntv; tp++) {
                    float vv = 0.f;
#pragma unroll
                    for (int w = 0; w < 8; w++) vv += wred2[w * TT + tp];
                    sl[tp] = vv;
                    mx = fmaxf(mx, vv);
                }
                float tot = 0.f;
                for (int tp = 0; tp < ntv; tp++) { float e = expf(sl[tp] - mx); sl[tp] = e; tot += e; }
                for (int tp = 0; tp < ntv; tp++) sattn[tp] = sl[tp] / tot;
                for (int tp = ntv; tp < TT; tp++) sattn[tp] = 0.f;
            }
            __syncthreads();
#pragma unroll
            for (int i = 0; i < 2; i++) {
                int d = tid + i * 256;
                float sv = 0.f;
                for (int tp = 0; tp <= t; tp++)
                    sv += sattn[tp] * g_mhist[(size_t)tp * BDSZ + (size_t)b * DD + d];
                g_msa[(size_t)b * DD + d] = sv;
            }
        }
        gbar(tgt);

        // ---- P3: U partials (v @ Wrm^T), 32 n-tiles x 4 chunks, KC=128 ----
        {
            int nt = blk & 31, ch = blk >> 5, kb = ch * 128;
            gtile(g_v + kb, DD, 0, P.Wrm + kb, DD, 1, nt * 32, 128,
                  g_p_U + (size_t)ch * BB * 2 * DD, 2 * DD, nullptr, sm);
        }
        gbar(tgt);

        // ---- P4: reduce U with mp epilogue ----
        {
            const size_t MN = (size_t)BB * 2 * DD;
            for (int idx = blk * NTHR + tid; idx < (int)MN; idx += NBLK * NTHR) {
                int n = idx & 1023, m = idx >> 10;
                float s = g_p_U[idx] + g_p_U[MN + idx] + g_p_U[2*MN + idx] + g_p_U[3*MN + idx];
                if (n < DD) {
                    int j = m * DD + n;
                    float mps = g_p_mp[j] + g_p_mp[BDSZ + j] + g_p_mp[2*BDSZ + j]
                              + g_p_mp[3*BDSZ + j] + P.bm[n];
                    s *= mps;
                }
                g_U[idx] = s;
            }
        }
        gbar(tgt);

        // ---- P5: z partials (64 blocks) || g partials (64 blocks), KC=128 ----
        {
            int b2 = blk & 63;
            int nt = b2 & 15, ch = b2 >> 4, kb = ch * 128;
            if (blk < 64)
                gtile(g_U + kb, 2 * DD, 0, P.Wkb + kb, DD, 1, nt * 32, 128,
                      g_p_z + (size_t)ch * BDSZ, DD, nullptr, sm);
            else
                gtile(chist_t1 + kb, DD, 0, P.Wg + (size_t)kb * DD, DD, 0,
                      nt * 32, 128, g_p_g + (size_t)ch * BDSZ, DD, nullptr, sm);
        }
        gbar(tgt);

        // ---- P6: read attention (block = batch) ----
        {
            int b = blk;
            float* zs  = sm;        // 512
            float* att = sm + 512;  // 196
            float* red = sm + 712;  // 16
#pragma unroll
            for (int i = 0; i < 2; i++) {
                int d = tid + i * 256;
                size_t j = (size_t)b * DD + d;
                float zv = g_U[(size_t)b * 2 * DD + DD + d];
                zv += g_p_z[j] + g_p_z[BDSZ + j] + g_p_z[2*BDSZ + j] + g_p_z[3*BDSZ + j];
                zs[d] = zv;
            }
            __syncthreads();
            const float* base = g_KBp + (size_t)b * HW * DD;
            for (int hw = warp; hw < HW; hw += 8) {
                const float4* row = (const float4*)(base + (size_t)hw * DD);
                const float4* z4 = (const float4*)zs;
                float acc = 0.f;
#pragma unroll
                for (int i = 0; i < 4; i++) {
                    float4 kv = row[lane + i * 32];
                    float4 zv = z4[lane + i * 32];
                    acc += kv.x*zv.x + kv.y*zv.y + kv.z*zv.z + kv.w*zv.w;
                }
                for (int off = 16; off; off >>= 1) acc += __shfl_down_sync(~0u, acc, off);
                if (lane == 0) att[hw] = acc;
            }
            __syncthreads();
            float val = (tid < HW) ? att[tid] : -1e30f;
            float m = val;
            for (int off = 16; off; off >>= 1) m = fmaxf(m, __shfl_xor_sync(~0u, m, off));
            if (lane == 0) red[warp] = m;
            __syncthreads();
            if (warp == 0) {
                float mm = (lane < 8) ? red[lane] : -1e30f;
                for (int off = 4; off; off >>= 1) mm = fmaxf(mm, __shfl_xor_sync(~0u, mm, off));
                if (lane == 0) red[0] = mm;
            }
            __syncthreads();
            float mx = red[0];
            float e = (tid < HW) ? expf(val - mx) : 0.f;
            float s_ = e;
            for (int off = 16; off; off >>= 1) s_ += __shfl_xor_sync(~0u, s_, off);
            if (lane == 0) red[8 + warp] = s_;
            __syncthreads();
            if (warp == 0) {
                float ss = (lane < 8) ? red[8 + lane] : 0.f;
                for (int off = 4; off; off >>= 1) ss += __shfl_xor_sync(~0u, ss, off);
                if (lane == 0) red[0] = ss;
            }
            __syncthreads();
            float inv = 1.f / red[0];
            if (tid < HW) att[tid] = e * inv;
            __syncthreads();
#pragma unroll
            for (int i = 0; i < 2; i++) {
                int d = tid + i * 256;
                const float* col = base + d;
                float acc = 0.f;
#pragma unroll 4
                for (int hw = 0; hw < HW; hw++) acc += att[hw] * col[(size_t)hw * DD];
                g_mnew[(size_t)b * DD + d] = acc;
            }
        }
        gbar(tgt);

        // ---- P7: final partials [msa|mnew|m_prev] @ Wcomb, 192 tiles, KC=128 ----
        for (int tile = blk; tile < 192; tile += NBLK) {
            int nt = tile & 15, ch = tile >> 4, kb = ch * 128;
            const float* A;
            if (kb < DD)            A = g_msa + kb;
            else if (kb < 2 * DD)   A = g_mnew + (kb - DD);
            else                    A = mhist_t + (kb - 2 * DD);
            gtile(A, DD, 0, g_Wcomb + (size_t)kb * DD, DD, 0, nt * 32, 128,
                  g_p_f + (size_t)ch * BDSZ, DD, nullptr, sm);
        }
        gbar(tgt);

        // ---- P8: reduce final + sigmoid gate ----
        for (int idx = blk * NTHR + tid; idx < BDSZ; idx += NBLK * NTHR) {
            int n = idx & 511;
            float m2 = g_bcomb[n];
#pragma unroll
            for (int c = 0; c < 12; c++) m2 += g_p_f[(size_t)c * BDSZ + idx];
            float gs = g_p_g[idx] + g_p_g[BDSZ + idx] + g_p_g[2*BDSZ + idx]
                     + g_p_g[3*BDSZ + idx] + P.bg[n];
            float gg = 1.f / (1.f + expf(-gs));
            float r = gg * mhist_t[idx] + (1.f - gg) * m2;
            mhist_t1[idx] = r;
            if (t == TT - 1) P.out[idx] = r;
        }
        gbar(tgt);
    }
}

// ---------------- host ----------------
extern "C" void kernel_launch(void* const* d_in, const int* in_sizes, int n_in,
                              void* d_out, int out_size)
{
    const float* q   = (const float*)d_in[0];
    const float* cws = (const float*)d_in[1];
    const float* KB  = (const float*)d_in[2];
    const float* c0  = (const float*)d_in[3];
    const float* m0  = (const float*)d_in[4];
    const float* Wq  = (const float*)d_in[5];
    const float* bq  = (const float*)d_in[6];
    const float* Wct = (const float*)d_in[7];
    const float* bct = (const float*)d_in[8];
    const float* wca = (const float*)d_in[9];
    const float* Wm  = (const float*)d_in[11];
    const float* bm  = (const float*)d_in[12];
    const float* Wkb = (const float*)d_in[13];
    const float* Wrm = (const float*)d_in[15];
    const float* wra = (const float*)d_in[17];
    const float* Wwm = (const float*)d_in[19];
    const float* bwm = (const float*)d_in[20];
    const float* wwa = (const float*)d_in[21];
    const float* Wam = (const float*)d_in[23];
    const float* bam = (const float*)d_in[24];
    const float* Wg  = (const float*)d_in[25];
    const float* bg  = (const float*)d_in[26];

    float *KBp, *chist, *mhist, *Wcomb;
    cudaGetSymbolAddress((void**)&KBp,   g_KBp);
    cudaGetSymbolAddress((void**)&chist, g_chist);
    cudaGetSymbolAddress((void**)&mhist, g_mhist);
    cudaGetSymbolAddress((void**)&Wcomb, g_Wcomb);

    reset_k<<<1, 1>>>();
    cudaMemcpyAsync(chist, c0, BDSZ * sizeof(float), cudaMemcpyDeviceToDevice);
    cudaMemcpyAsync(mhist, m0, BDSZ * sizeof(float), cudaMemcpyDeviceToDevice);
    cudaMemcpyAsync(Wcomb, Wam, (size_t)DD * DD * sizeof(float), cudaMemcpyDeviceToDevice);
    transpose_kb_k<<<dim3((HW + 31) / 32, DD / 32, BB), dim3(32, 8)>>>(KB, KBp);

    MP P;
    P.q = q; P.cws = cws; P.Wq = Wq; P.bq = bq; P.Wct = Wct; P.bct = bct;
    P.wca = wca; P.Wm = Wm; P.bm = bm; P.Wkb = Wkb; P.Wrm = Wrm; P.wra = wra;
    P.Wwm = Wwm; P.bwm = bwm; P.wwa = wwa; P.Wam = Wam; P.bam = bam;
    P.Wg = Wg; P.bg = bg; P.out = (float*)d_out;

    mega_k<<<NBLK, NTHR>>>(P);
}

// round 7
// speedup vs baseline: 1.1885x; 1.1885x over previous
#include <cuda_runtime.h>
#include <math.h>

// ---------------- problem constants ----------------
#define BB   128
#define DD   512
#define SS   30
#define HW   196
#define TT   12
#define NH   13
#define BDSZ (BB*DD)
#define U2D  (BB*2*DD)

// ---------------- device scratch ----------------
__device__ float g_KBp[(size_t)BB*HW*DD];
__device__ float g_chist[(size_t)NH*BDSZ];
__device__ float g_mhist[(size_t)NH*BDSZ];
__device__ float g_qi[BDSZ];
__device__ float g_cq0[BDSZ];
__device__ float g_v[BDSZ];
__device__ float g_mnew[BDSZ];
__device__ float g_msa[BDSZ];
__device__ float g_Wcomb[(size_t)3*DD*DD];
__device__ float g_bcomb[DD];
__device__ float g_p_cq[(size_t)4*BDSZ];
__device__ float g_p_mp[(size_t)4*BDSZ];
__device__ float g_p_U [(size_t)4*U2D];
__device__ float g_p_g [(size_t)4*BDSZ];
__device__ float g_p_z [(size_t)4*BDSZ];
__device__ float g_p_f [(size_t)12*BDSZ];
__device__ float g_p_set[(size_t)4*1024*DD];

#define SMSZ (16*132 + 16*36)

// ---------------- 128x32 GEMM tile over a KC k-range ----------------
// A pre-offset to k-base. wtrans=0: W (K,N) row-major pre-offset kbase*ldw;
// wtrans=1: W (N,K) row-major pre-offset kbase.
__device__ __noinline__ void gtile(
    const float* __restrict__ A, int lda, int m0,
    const float* __restrict__ W, int ldw, int wtrans,
    int n0, int KC,
    float* __restrict__ out, int ldo, const float* __restrict__ bias,
    float* sm)
{
    float (*As)[132] = (float(*)[132])sm;
    float (*Ws)[36]  = (float(*)[36])(sm + 16*132);
    int tid = threadIdx.x;
    int tx = tid & 7, tg = tid >> 3;
    int lm = tid >> 1, lk = (tid & 1) * 8;
    float acc[4][4];
#pragma unroll
    for (int i = 0; i < 4; i++)
#pragma unroll
        for (int j = 0; j < 4; j++) acc[i][j] = 0.f;

    for (int kt = 0; kt < KC; kt += 16) {
        const float* ap = A + (size_t)(m0 + lm) * lda + kt + lk;
        float4 a0 = *(const float4*)ap;
        float4 a1 = *(const float4*)(ap + 4);
        float w0, w1;
        if (wtrans) {
            int wn = tid >> 3, wk = (tid & 7) * 2;
            const float* wp = W + (size_t)(n0 + wn) * ldw + kt + wk;
            w0 = wp[0]; w1 = wp[1];
        } else {
            int wk = tid >> 4, wn = tid & 15;
            const float* wp = W + (size_t)(kt + wk) * ldw + n0 + wn;
            w0 = wp[0]; w1 = wp[16];
        }
        __syncthreads();
        As[lk+0][lm]=a0.x; As[lk+1][lm]=a0.y; As[lk+2][lm]=a0.z; As[lk+3][lm]=a0.w;
        As[lk+4][lm]=a1.x; As[lk+5][lm]=a1.y; As[lk+6][lm]=a1.z; As[lk+7][lm]=a1.w;
        if (wtrans) {
            int wn = tid >> 3, wk = (tid & 7) * 2;
            Ws[wk][wn] = w0; Ws[wk+1][wn] = w1;
        } else {
            int wk = tid >> 4, wn = tid & 15;
            Ws[wk][wn] = w0; Ws[wk][wn+16] = w1;
        }
        __syncthreads();
#pragma unroll
        for (int kk = 0; kk < 16; kk++) {
            float4 a = *(const float4*)&As[kk][tg*4];
            float4 w = *(const float4*)&Ws[kk][tx*4];
            acc[0][0]+=a.x*w.x; acc[0][1]+=a.x*w.y; acc[0][2]+=a.x*w.z; acc[0][3]+=a.x*w.w;
            acc[1][0]+=a.y*w.x; acc[1][1]+=a.y*w.y; acc[1][2]+=a.y*w.z; acc[1][3]+=a.y*w.w;
            acc[2][0]+=a.z*w.x; acc[2][1]+=a.z*w.y; acc[2][2]+=a.z*w.z; acc[2][3]+=a.z*w.w;
            acc[3][0]+=a.w*w.x; acc[3][1]+=a.w*w.y; acc[3][2]+=a.w*w.z; acc[3][3]+=a.w*w.w;
        }
    }
    float* po = out + (size_t)(m0 + tg*4) * ldo + n0 + tx*4;
#pragma unroll
    for (int i = 0; i < 4; i++) {
        float4 r = make_float4(acc[i][0], acc[i][1], acc[i][2], acc[i][3]);
        if (bias) {
            int c = n0 + tx*4;
            r.x += bias[c]; r.y += bias[c+1]; r.z += bias[c+2]; r.w += bias[c+3];
        }
        *(float4*)(po + (size_t)i * ldo) = r;
    }
}

// ---------------- z-variant: A computed on the fly, y = (Σ4 pU)·(Σ4 pmp + bm) ----------------
__device__ __noinline__ void gtileZ(
    const float* __restrict__ Wkb, int n0, int kbz,
    float* __restrict__ outp, const float* __restrict__ bm, float* sm)
{
    float (*As)[132] = (float(*)[132])sm;
    float (*Ws)[36]  = (float(*)[36])(sm + 16*132);
    int tid = threadIdx.x;
    int tx = tid & 7, tg = tid >> 3;
    int lm = tid >> 1, lk = (tid & 1) * 8;
    float acc[4][4];
#pragma unroll
    for (int i = 0; i < 4; i++)
#pragma unroll
        for (int j = 0; j < 4; j++) acc[i][j] = 0.f;

    for (int kt = 0; kt < 128; kt += 16) {
        int k = kbz + kt + lk;
        size_t o2 = (size_t)lm * (2*DD) + k;
        size_t o1 = (size_t)lm * DD + k;
        float4 a0, a1;
#pragma unroll
        for (int h = 0; h < 2; h++) {
            size_t q2 = o2 + h*4, q1 = o1 + h*4;
            float4 u0 = *(const float4*)(g_p_U + q2);
            float4 u1 = *(const float4*)(g_p_U + (size_t)U2D + q2);
            float4 u2 = *(const float4*)(g_p_U + (size_t)2*U2D + q2);
            float4 u3 = *(const float4*)(g_p_U + (size_t)3*U2D + q2);
            float4 m0v = *(const float4*)(g_p_mp + q1);
            float4 m1v = *(const float4*)(g_p_mp + (size_t)BDSZ + q1);
            float4 m2v = *(const float4*)(g_p_mp + (size_t)2*BDSZ + q1);
            float4 m3v = *(const float4*)(g_p_mp + (size_t)3*BDSZ + q1);
            float4 bv  = *(const float4*)(bm + k + h*4);
            float4 r;
            r.x = (u0.x+u1.x+u2.x+u3.x) * (m0v.x+m1v.x+m2v.x+m3v.x+bv.x);
            r.y = (u0.y+u1.y+u2.y+u3.y) * (m0v.y+m1v.y+m2v.y+m3v.y+bv.y);
            r.z = (u0.z+u1.z+u2.z+u3.z) * (m0v.z+m1v.z+m2v.z+m3v.z+bv.z);
            r.w = (u0.w+u1.w+u2.w+u3.w) * (m0v.w+m1v.w+m2v.w+m3v.w+bv.w);
            if (h == 0) a0 = r; else a1 = r;
        }
        int wn = tid >> 3, wk = (tid & 7) * 2;
        const float* wp = Wkb + kbz + (size_t)(n0 + wn) * DD + kt + wk;
        float w0 = wp[0], w1 = wp[1];
        __syncthreads();
        As[lk+0][lm]=a0.x; As[lk+1][lm]=a0.y; As[lk+2][lm]=a0.z; As[lk+3][lm]=a0.w;
        As[lk+4][lm]=a1.x; As[lk+5][lm]=a1.y; As[lk+6][lm]=a1.z; As[lk+7][lm]=a1.w;
        Ws[wk][wn] = w0; Ws[wk+1][wn] = w1;
        __syncthreads();
#pragma unroll
        for (int kk = 0; kk < 16; kk++) {
            float4 a = *(const float4*)&As[kk][tg*4];
            float4 w = *(const float4*)&Ws[kk][tx*4];
            acc[0][0]+=a.x*w.x; acc[0][1]+=a.x*w.y; acc[0][2]+=a.x*w.z; acc[0][3]+=a.x*w.w;
            acc[1][0]+=a.y*w.x; acc[1][1]+=a.y*w.y; acc[1][2]+=a.y*w.z; acc[1][3]+=a.y*w.w;
            acc[2][0]+=a.z*w.x; acc[2][1]+=a.z*w.y; acc[2][2]+=a.z*w.z; acc[2][3]+=a.z*w.w;
            acc[3][0]+=a.w*w.x; acc[3][1]+=a.w*w.y; acc[3][2]+=a.w*w.z; acc[3][3]+=a.w*w.w;
        }
    }
    float* po = outp + (size_t)(tg*4) * DD + n0 + tx*4;
#pragma unroll
    for (int i = 0; i < 4; i++)
        *(float4*)(po + (size_t)i * DD) =
            make_float4(acc[i][0], acc[i][1], acc[i][2], acc[i][3]);
}

// ---------------- setup: generic split-K partial GEMM ----------------
struct GP {
    const float* A; int lda; int K;
    const float* W; int wtrans; int ldw;
    float* part; int M; int N; int KC;
};
__global__ void __launch_bounds__(256) gpartial_k(const GP P)
{
    __shared__ float sm[SMSZ];
    int ntiles = P.N >> 5;
    int nt = blockIdx.x % ntiles;
    int mt = blockIdx.x / ntiles;
    int kb = blockIdx.y * P.KC;
    gtile(P.A + kb, P.lda, mt * 128,
          P.wtrans ? (P.W + kb) : (P.W + (size_t)kb * P.ldw), P.ldw, P.wtrans,
          nt * 32, P.KC,
          P.part + (size_t)blockIdx.y * P.M * P.N, P.N, nullptr, sm);
}
__global__ void reduce0_k(const float* __restrict__ part, int nch, int MN, int N,
                          const float* __restrict__ bias, float* __restrict__ out)
{
    int idx = blockIdx.x * 256 + threadIdx.x;
    if (idx >= MN) return;
    float s = 0.f;
    for (int c = 0; c < nch; c++) s += part[(size_t)c * MN + idx];
    if (bias) s += bias[idx % N];
    out[idx] = s;
}

// ---------------- transpose KB (B,D,HW) -> KBp (B,HW,D) ----------------
__global__ void transpose_kb_k(const float* __restrict__ KB, float* __restrict__ KBp)
{
    __shared__ float tile[32][33];
    int b = blockIdx.z;
    int hw0 = blockIdx.x * 32, d0 = blockIdx.y * 32;
    int tx = threadIdx.x, ty = threadIdx.y;
    const float* src = KB + (size_t)b * DD * HW;
#pragma unroll
    for (int j = 0; j < 4; j++) {
        int d = d0 + ty + j * 8;
        int hw = hw0 + tx;
        if (hw < HW) tile[ty + j * 8][tx] = src[(size_t)d * HW + hw];
    }
    __syncthreads();
    float* dst = KBp + (size_t)b * HW * DD;
#pragma unroll
    for (int j = 0; j < 4; j++) {
        int hw = hw0 + ty + j * 8;
        if (hw < HW) dst[(size_t)hw * DD + d0 + tx] = tile[tx][ty + j * 8];
    }
}

// ---------------- bcomb = bwm @ Wam_bot + bam ----------------
__global__ void bcomb_k(const float* __restrict__ Wam, const float* __restrict__ bwm,
                        const float* __restrict__ bam)
{
    int n = blockIdx.x * 128 + threadIdx.x;
    float s = bam[n];
#pragma unroll 8
    for (int j = 0; j < DD; j++) s += bwm[j] * Wam[(size_t)(DD + j) * DD + n];
    g_bcomb[n] = s;
}

// ---------------- merged control + self attention (per-batch block) ----------------
__global__ void __launch_bounds__(128)
attn1_k(const float* __restrict__ cws, const float* __restrict__ wca,
        const float* __restrict__ wra, const float* __restrict__ wwa, int t)
{
    int b = blockIdx.x, tid = threadIdx.x;
    int lane = tid & 31, warp = tid >> 5;

    float accs[SS];
#pragma unroll
    for (int s = 0; s < SS; s++) accs[s] = 0.f;
#pragma unroll
    for (int i = 0; i < 4; i++) {
        int d = tid + i * 128;
        size_t j = (size_t)b * DD + d;
        float cqv = g_p_cq[j] + g_p_cq[BDSZ + j] + g_p_cq[2*BDSZ + j]
                  + g_p_cq[3*BDSZ + j] + g_cq0[j];
        float a = cqv * wca[d];
        const float* row = cws + j * SS;
#pragma unroll
        for (int s = 0; s < SS; s++) accs[s] += a * row[s];
    }
    __shared__ float wred[4][SS];
#pragma unroll
    for (int s = 0; s < SS; s++) {
        float x = accs[s];
        for (int off = 16; off; off >>= 1) x += __shfl_down_sync(~0u, x, off);
        if (lane == 0) wred[warp][s] = x;
    }
    __syncthreads();
    __shared__ float cattn[SS];
    if (warp == 0) {
        float val = (lane < SS) ? (wred[0][lane] + wred[1][lane] + wred[2][lane] + wred[3][lane]) : -1e30f;
        float mx = val;
        for (int off = 16; off; off >>= 1) mx = fmaxf(mx, __shfl_xor_sync(~0u, mx, off));
        float e = (lane < SS) ? expf(val - mx) : 0.f;
        float tot = e;
        for (int off = 16; off; off >>= 1) tot += __shfl_xor_sync(~0u, tot, off);
        if (lane < SS) cattn[lane] = e / tot;
    }
    __syncthreads();

    float ci[4];
#pragma unroll
    for (int i = 0; i < 4; i++) {
        int d = tid + i * 128;
        const float* row = cws + ((size_t)b * DD + d) * SS;
        float c = 0.f;
#pragma unroll
        for (int s = 0; s < SS; s++) c += cattn[s] * row[s];
        ci[i] = c;
        g_chist[(size_t)(t + 1) * BDSZ + (size_t)b * DD + d] = c;
        g_v[(size_t)b * DD + d] = c * wra[d];
    }

    float aw[4];
#pragma unroll
    for (int i = 0; i < 4; i++) aw[i] = ci[i] * wwa[tid + i * 128];
    float acct[TT];
#pragma unroll
    for (int tp = 0; tp < TT; tp++) acct[tp] = 0.f;
    for (int tp = 0; tp <= t; tp++) {
        const float* ch = g_chist + (size_t)tp * BDSZ + (size_t)b * DD;
        acct[tp] = aw[0] * ch[tid] + aw[1] * ch[tid + 128]
                 + aw[2] * ch[tid + 256] + aw[3] * ch[tid + 384];
    }
    __shared__ float wred2[4][TT];
#pragma unroll
    for (int tp = 0; tp < TT; tp++) {
        float x = acct[tp];
        for (int off = 16; off; off >>= 1) x += __shfl_down_sync(~0u, x, off);
        if (lane == 0) wred2[warp][tp] = x;
    }
    __syncthreads();
    __shared__ float sattn[TT];
    if (tid == 0) {
        int ntv = t + 1;
        float sl[TT];
        float mx = -1e30f;
        for (int tp = 0; tp < ntv; tp++) {
            float vv = wred2[0][tp] + wred2[1][tp] + wred2[2][tp] + wred2[3][tp];
            sl[tp] = vv;
            mx = fmaxf(mx, vv);
        }
        float tot = 0.f;
        for (int tp = 0; tp < ntv; tp++) { float e = expf(sl[tp] - mx); sl[tp] = e; tot += e; }
        for (int tp = 0; tp < ntv; tp++) sattn[tp] = sl[tp] / tot;
        for (int tp = ntv; tp < TT; tp++) sattn[tp] = 0.f;
    }
    __syncthreads();
#pragma unroll
    for (int i = 0; i < 4; i++) {
        int d = tid + i * 128;
        float sv = 0.f;
        for (int tp = 0; tp <= t; tp++)
            sv += sattn[tp] * g_mhist[(size_t)tp * BDSZ + (size_t)b * DD + d];
        g_msa[(size_t)b * DD + d] = sv;
    }
}

// ---------------- kB: U partials + cq_{t+1} partials + mp partials (256 blocks) ----------------
__global__ void __launch_bounds__(256)
kB_k(const float* ci, const float* mprev,
     const float* __restrict__ Wrm, const float* __restrict__ Wct,
     const float* __restrict__ Wm)
{
    __shared__ float sm[SMSZ];
    int blk = blockIdx.x;
    if (blk < 128) {
        int nt = blk & 31, ch = blk >> 5, kb = ch * 128;
        gtile(g_v + kb, DD, 0, Wrm + kb, DD, 1, nt * 32, 128,
              g_p_U + (size_t)ch * U2D, 2 * DD, nullptr, sm);
    } else if (blk < 192) {
        int b2 = blk - 128, nt = b2 & 15, ch = b2 >> 4, kb = ch * 128;
        gtile(ci + kb, DD, 0, Wct + (size_t)(DD + kb) * DD, DD, 0, nt * 32, 128,
              g_p_cq + (size_t)ch * BDSZ, DD, nullptr, sm);
    } else {
        int b2 = blk - 192, nt = b2 & 15, ch = b2 >> 4, kb = ch * 128;
        gtile(mprev + kb, DD, 0, Wm + (size_t)kb * DD, DD, 0, nt * 32, 128,
              g_p_mp + (size_t)ch * BDSZ, DD, nullptr, sm);
    }
}

// ---------------- kC: z partials (on-the-fly y) + g partials (128 blocks) ----------------
__global__ void __launch_bounds__(256)
kC_k(const float* ci, const float* __restrict__ Wkb,
     const float* __restrict__ Wg, const float* __restrict__ bm)
{
    __shared__ float sm[SMSZ];
    int blk = blockIdx.x;
    if (blk < 64) {
        int nt = blk & 15, ch = blk >> 4, kb = ch * 128;
        gtileZ(Wkb, nt * 32, kb, g_p_z + (size_t)ch * BDSZ, bm, sm);
    } else {
        int b2 = blk - 64, nt = b2 & 15, ch = b2 >> 4, kb = ch * 128;
        gtile(ci + kb, DD, 0, Wg + (size_t)kb * DD, DD, 0, nt * 32, 128,
              g_p_g + (size_t)ch * BDSZ, DD, nullptr, sm);
    }
}

// ---------------- read attention (sums z partials + u2 from pU) ----------------
__global__ void __launch_bounds__(512)
read_attn_k()
{
    int b = blockIdx.x, tid = threadIdx.x;
    __shared__ float zs[DD];
    __shared__ float att[HW];
    __shared__ float red[16];
    {
        size_t j = (size_t)b * DD + tid;
        size_t j2 = (size_t)b * 2 * DD + DD + tid;
        float zv = g_p_z[j] + g_p_z[BDSZ + j] + g_p_z[2*BDSZ + j] + g_p_z[3*BDSZ + j]
                 + g_p_U[j2] + g_p_U[(size_t)U2D + j2]
                 + g_p_U[(size_t)2*U2D + j2] + g_p_U[(size_t)3*U2D + j2];
        zs[tid] = zv;
    }
    __syncthreads();
    int warp = tid >> 5, lane = tid & 31;
    const float* base = g_KBp + (size_t)b * HW * DD;
    for (int hw = warp; hw < HW; hw += 16) {
        const float4* row = (const float4*)(base + (size_t)hw * DD);
        const float4* z4 = (const float4*)zs;
        float acc = 0.f;
#pragma unroll
        for (int i = 0; i < 4; i++) {
            float4 kv = row[lane + i * 32];
            float4 zv = z4[lane + i * 32];
            acc += kv.x*zv.x + kv.y*zv.y + kv.z*zv.z + kv.w*zv.w;
        }
        for (int off = 16; off; off >>= 1) acc += __shfl_down_sync(~0u, acc, off);
        if (lane == 0) att[hw] = acc;
    }
    __syncthreads();
    float val = (tid < HW) ? att[tid] : -1e30f;
    float m = val;
    for (int off = 16; off; off >>= 1) m = fmaxf(m, __shfl_xor_sync(~0u, m, off));
    if (lane == 0) red[warp] = m;
    __syncthreads();
    if (warp == 0) {
        float mm = (lane < 16) ? red[lane] : -1e30f;
        for (int off = 8; off; off >>= 1) mm = fmaxf(mm, __shfl_xor_sync(~0u, mm, off));
        if (lane == 0) red[0] = mm;
    }
    __syncthreads();
    float mx = red[0];
    float e = (tid < HW) ? expf(val - mx) : 0.f;
    float s = e;
    for (int off = 16; off; off >>= 1) s += __shfl_xor_sync(~0u, s, off);
    __syncthreads();
    if (lane == 0) red[warp] = s;
    __syncthreads();
    if (warp == 0) {
        float ss = (lane < 16) ? red[lane] : 0.f;
        for (int off = 8; off; off >>= 1) ss += __shfl_xor_sync(~0u, ss, off);
        if (lane == 0) red[0] = ss;
    }
    __syncthreads();
    float inv = 1.f / red[0];
    if (tid < HW) att[tid] = e * inv;
    __syncthreads();
    const float* col = base + tid;
    float acc = 0.f;
#pragma unroll 4
    for (int hw = 0; hw < HW; hw++) acc += att[hw] * col[(size_t)hw * DD];
    g_mnew[(size_t)b * DD + tid] = acc;
}

// ---------------- kE: final partials [msa|mnew|m_prev] @ Wcomb (192 blocks) ----------------
__global__ void __launch_bounds__(256)
kE_k(const float* mprev)
{
    __shared__ float sm[SMSZ];
    int tile = blockIdx.x;
    int nt = tile & 15, ch = tile >> 4, kb = ch * 128;
    const float* A;
    if (kb < DD)            A = g_msa + kb;
    else if (kb < 2 * DD)   A = g_mnew + (kb - DD);
    else                    A = mprev + (kb - 2 * DD);
    gtile(A, DD, 0, g_Wcomb + (size_t)kb * DD, DD, 0, nt * 32, 128,
          g_p_f + (size_t)ch * BDSZ, DD, nullptr, sm);
}

// ---------------- kF: reduce final + sigmoid gate ----------------
__global__ void gateF_k(const float* __restrict__ bg, const float* mprev,
                        float* mnext, float* out, int writeOut)
{
    int idx = blockIdx.x * 256 + threadIdx.x;
    int n = idx & 511;
    float m2 = g_bcomb[n];
#pragma unroll
    for (int c = 0; c < 12; c++) m2 += g_p_f[(size_t)c * BDSZ + idx];
    float gs = g_p_g[idx] + g_p_g[BDSZ + idx] + g_p_g[2*BDSZ + idx]
             + g_p_g[3*BDSZ + idx] + bg[n];
    float gg = 1.f / (1.f + expf(-gs));
    float r = gg * mprev[idx] + (1.f - gg) * m2;
    mnext[idx] = r;
    if (writeOut) out[idx] = r;
}

// ---------------- host ----------------
extern "C" void kernel_launch(void* const* d_in, const int* in_sizes, int n_in,
                              void* d_out, int out_size)
{
    const float* q   = (const float*)d_in[0];
    const float* cws = (const float*)d_in[1];
    const float* KB  = (const float*)d_in[2];
    const float* c0  = (const float*)d_in[3];
    const float* m0  = (const float*)d_in[4];
    const float* Wq  = (const float*)d_in[5];
    const float* bq  = (const float*)d_in[6];
    const float* Wct = (const float*)d_in[7];
    const float* bct = (const float*)d_in[8];
    const float* wca = (const float*)d_in[9];
    const float* Wm  = (const float*)d_in[11];
    const float* bm  = (const float*)d_in[12];
    const float* Wkb = (const float*)d_in[13];
    const float* Wrm = (const float*)d_in[15];
    const float* wra = (const float*)d_in[17];
    const float* Wwm = (const float*)d_in[19];
    const float* bwm = (const float*)d_in[20];
    const float* wwa = (const float*)d_in[21];
    const float* Wam = (const float*)d_in[23];
    const float* bam = (const float*)d_in[24];
    const float* Wg  = (const float*)d_in[25];
    const float* bg  = (const float*)d_in[26];

    float *KBp, *chist, *mhist, *qi, *cq0, *Wcomb, *p_set, *p_cq;
    cudaGetSymbolAddress((void**)&KBp,   g_KBp);
    cudaGetSymbolAddress((void**)&chist, g_chist);
    cudaGetSymbolAddress((void**)&mhist, g_mhist);
    cudaGetSymbolAddress((void**)&qi,    g_qi);
    cudaGetSymbolAddress((void**)&cq0,   g_cq0);
    cudaGetSymbolAddress((void**)&Wcomb, g_Wcomb);
    cudaGetSymbolAddress((void**)&p_set, g_p_set);
    cudaGetSymbolAddress((void**)&p_cq,  g_p_cq);

    // ---- setup ----
    cudaMemcpyAsync(chist, c0, BDSZ * sizeof(float), cudaMemcpyDeviceToDevice);
    cudaMemcpyAsync(mhist, m0, BDSZ * sizeof(float), cudaMemcpyDeviceToDevice);
    cudaMemcpyAsync(Wcomb, Wam, (size_t)DD * DD * sizeof(float), cudaMemcpyDeviceToDevice);

    transpose_kb_k<<<dim3((HW + 31) / 32, DD / 32, BB), dim3(32, 8)>>>(KB, KBp);
    bcomb_k<<<4, 128>>>(Wam, bwm, bam);

    GP p;
    // qi = q @ Wq + bq
    p = {q, DD, DD, Wq, 0, DD, p_set, BB, DD, 128};
    gpartial_k<<<dim3(16, 4), 256>>>(p);
    reduce0_k<<<BDSZ / 256, 256>>>(p_set, 4, BDSZ, DD, bq, qi);
    // cq0 = qi @ Wct_top + bct
    p = {qi, DD, DD, Wct, 0, DD, p_set, BB, DD, 128};
    gpartial_k<<<dim3(16, 4), 256>>>(p);
    reduce0_k<<<BDSZ / 256, 256>>>(p_set, 4, BDSZ, DD, bct, cq0);
    // Wcomb rows 512..1535 = Wwm @ Wam_bot
    p = {Wwm, DD, DD, Wam + (size_t)DD * DD, 0, DD, p_set, 2 * DD, DD, 128};
    gpartial_k<<<dim3(16 * 8, 4), 256>>>(p);
    reduce0_k<<<(2 * DD * DD) / 256, 256>>>(p_set, 4, 2 * DD * DD, DD, nullptr,
                                            Wcomb + (size_t)DD * DD);
    // cq partials for t=0: c0 @ Wct_bot
    p = {chist, DD, DD, Wct + (size_t)DD * DD, 0, DD, p_cq, BB, DD, 128};
    gpartial_k<<<dim3(16, 4), 256>>>(p);

    // ---- main recurrence: 6 launches per step ----
    for (int t = 0; t < TT; t++) {
        const float* mhist_t  = mhist + (size_t)t * BDSZ;
        float*       mhist_t1 = mhist + (size_t)(t + 1) * BDSZ;
        const float* ci_cur   = chist + (size_t)(t + 1) * BDSZ;

        attn1_k<<<BB, 128>>>(cws, wca, wra, wwa, t);
        kB_k<<<256, 256>>>(ci_cur, mhist_t, Wrm, Wct, Wm);
        kC_k<<<128, 256>>>(ci_cur, Wkb, Wg, bm);
        read_attn_k<<<BB, 512>>>();
        kE_k<<<192, 256>>>(mhist_t);
        gateF_k<<<BDSZ / 256, 256>>>(bg, mhist_t, mhist_t1, (float*)d_out,
                                     (t == TT - 1) ? 1 : 0);
    }
}